// round 8
// baseline (speedup 1.0000x reference)
#include <cuda_runtime.h>

#define N_NODES 100000
#define D       64
#define N_EDGES 1250000

// ---- scratch (allocation-free rule: __device__ globals) ----
__device__ __align__(16) float g_agg[N_NODES * D];   // scatter-sum of X[src] at dst
__device__ __align__(16) float g_h[N_NODES * D];     // relu(agg@Wl + b + X@Wr)
__device__ __align__(16) float g_gg[N_NODES * D];    // scatter-sum of diff^2 at src
__device__ float g_indeg[N_NODES];
__device__ float g_outdeg[N_NODES];
__device__ int   g_idx64;                            // 1 if edge_index is int64

// Vectorized global reduction: one RED.128 instead of 4 scalar REDGs.
__device__ __forceinline__ void red_add_v4(float* dst, float a, float b,
                                           float c, float d) {
    asm volatile(
        "{\n\t"
        ".reg .u64 p;\n\t"
        "cvta.to.global.u64 p, %0;\n\t"
        "red.global.add.v4.f32 [p], {%1, %2, %3, %4};\n\t"
        "}"
        :: "l"(dst), "f"(a), "f"(b), "f"(c), "f"(d)
        : "memory");
}

// Edge accessor robust to int32-vs-int64 edge_index.
__device__ __forceinline__ void load_edge(const void* __restrict__ ei,
                                          long long e, int is64,
                                          int& r, int& c) {
    if (is64) {
        const long long* p = (const long long*)ei;
        r = (int)p[e];
        c = (int)p[N_EDGES + e];
    } else {
        const int* p = (const int*)ei;
        r = p[e];
        c = p[N_EDGES + e];
    }
}

// ---------------------------------------------------------------------------
// K0: zero accumulators + (block 0) dtype detect. Runs every graph replay.
// ---------------------------------------------------------------------------
__global__ void k_zero(const long long* __restrict__ ei64) {
    if (blockIdx.x == 0 && threadIdx.x == 0) {
        int ok = 1;
        for (int i = 0; i < 32; i++) {
            long long v = ei64[i];
            if (v < 0 || v >= N_NODES) { ok = 0; break; }
        }
        g_idx64 = ok;
    }
    int i = blockIdx.x * blockDim.x + threadIdx.x;
    int stride = gridDim.x * blockDim.x;
    float4 z = make_float4(0.f, 0.f, 0.f, 0.f);
    float4* a4 = reinterpret_cast<float4*>(g_agg);
    float4* g4 = reinterpret_cast<float4*>(g_gg);
    const int n4 = N_NODES * D / 4;
    for (int idx = i; idx < n4; idx += stride) { a4[idx] = z; g4[idx] = z; }
    for (int idx = i; idx < N_NODES; idx += stride) { g_indeg[idx] = 0.f; g_outdeg[idx] = 0.f; }
}

// ---------------------------------------------------------------------------
// K2: scatter-sum X[row] into g_agg[col] + fused in-degree count.
// ---------------------------------------------------------------------------
__global__ void k_scatter(const float4* __restrict__ X4,
                          const void* __restrict__ ei) {
    long long gtid = (long long)blockIdx.x * blockDim.x + threadIdx.x;
    long long e = gtid >> 4;
    int l = (int)(gtid & 15);
    if (e >= N_EDGES) return;
    int is64 = g_idx64;
    int r, c;
    load_edge(ei, e, is64, r, c);
    float4 v = X4[(long long)r * 16 + l];
    red_add_v4(&g_agg[(long long)c * 64 + l * 4], v.x, v.y, v.z, v.w);
    if (l == 0) atomicAdd(&g_indeg[c], 1.f);
}

// ---------------------------------------------------------------------------
// K3: h = relu( (agg/indeg) @ Wl + b + X @ Wr ).
// 128-node tile / block, 256 threads, thread = 8 nodes x 4 outputs.
// Inner loop per k: 6 x LDS.128 -> 64 FFMA.
// Dynamic smem (floats): sWl[4096] sWr[4096] saT[8192] sxT[8192]  (96 KB)
//   saT/sxT are k-major: saT[k*128 + n].
// ---------------------------------------------------------------------------
__global__ __launch_bounds__(256) void k_h(const float* __restrict__ X,
                                           const float* __restrict__ Wl,
                                           const float* __restrict__ Wr,
                                           const float* __restrict__ b) {
    extern __shared__ float s[];
    float* sWl = s;
    float* sWr = s + 4096;
    float* saT = s + 8192;
    float* sxT = s + 16384;

    int t = threadIdx.x;
    for (int i = t; i < 4096; i += 256) { sWl[i] = Wl[i]; sWr[i] = Wr[i]; }

    const int jq = t & 15;        // outputs jq*4 .. jq*4+3
    const int ng = t >> 4;        // nodes ng*8 .. ng*8+7 (within 128-node tile)
    const float4 bias = reinterpret_cast<const float4*>(b)[jq];
    __syncthreads();

    const float4* A4 = reinterpret_cast<const float4*>(g_agg);
    const float4* X4 = reinterpret_cast<const float4*>(X);

    for (int base = blockIdx.x * 128; base < N_NODES; base += gridDim.x * 128) {
        // ---- load 128-node tile, transposed, 1/indeg folded in ----
#pragma unroll
        for (int p = 0; p < 8; p++) {
            int fi = t + p * 256;          // 0..2047
            int node = fi & 127;
            int kq = fi >> 7;              // 0..15 (float4 index along k)
            int gnode = base + node;
            float4 va, vx;
            if (gnode < N_NODES) {
                float invd = 1.f / fmaxf(g_indeg[gnode], 1.f);
                va = A4[(long long)gnode * 16 + kq];
                vx = X4[(long long)gnode * 16 + kq];
                va.x *= invd; va.y *= invd; va.z *= invd; va.w *= invd;
            } else {
                va = make_float4(0.f, 0.f, 0.f, 0.f);
                vx = va;
            }
            int kb = kq * 4;
            saT[(kb + 0) * 128 + node] = va.x;
            saT[(kb + 1) * 128 + node] = va.y;
            saT[(kb + 2) * 128 + node] = va.z;
            saT[(kb + 3) * 128 + node] = va.w;
            sxT[(kb + 0) * 128 + node] = vx.x;
            sxT[(kb + 1) * 128 + node] = vx.y;
            sxT[(kb + 2) * 128 + node] = vx.z;
            sxT[(kb + 3) * 128 + node] = vx.w;
        }
        __syncthreads();

        // ---- compute 8x4 register block ----
        float acc[8][4];
#pragma unroll
        for (int i = 0; i < 8; i++) {
            acc[i][0] = bias.x; acc[i][1] = bias.y;
            acc[i][2] = bias.z; acc[i][3] = bias.w;
        }
#pragma unroll 4
        for (int k = 0; k < 64; k++) {
            const float* saRow = &saT[k * 128 + ng * 8];
            const float* sxRow = &sxT[k * 128 + ng * 8];
            float4 a0 = *reinterpret_cast<const float4*>(saRow);
            float4 a1 = *reinterpret_cast<const float4*>(saRow + 4);
            float4 x0 = *reinterpret_cast<const float4*>(sxRow);
            float4 x1 = *reinterpret_cast<const float4*>(sxRow + 4);
            float4 wl = *reinterpret_cast<const float4*>(&sWl[k * 64 + jq * 4]);
            float4 wr = *reinterpret_cast<const float4*>(&sWr[k * 64 + jq * 4]);
            float av[8] = {a0.x, a0.y, a0.z, a0.w, a1.x, a1.y, a1.z, a1.w};
            float xv[8] = {x0.x, x0.y, x0.z, x0.w, x1.x, x1.y, x1.z, x1.w};
            float wlv[4] = {wl.x, wl.y, wl.z, wl.w};
            float wrv[4] = {wr.x, wr.y, wr.z, wr.w};
#pragma unroll
            for (int i = 0; i < 8; i++)
#pragma unroll
                for (int j = 0; j < 4; j++)
                    acc[i][j] += av[i] * wlv[j] + xv[i] * wrv[j];
        }

        // ---- store with ReLU ----
#pragma unroll
        for (int i = 0; i < 8; i++) {
            int node = base + ng * 8 + i;
            if (node < N_NODES) {
                float4 o;
                o.x = fmaxf(acc[i][0], 0.f);
                o.y = fmaxf(acc[i][1], 0.f);
                o.z = fmaxf(acc[i][2], 0.f);
                o.w = fmaxf(acc[i][3], 0.f);
                reinterpret_cast<float4*>(&g_h[(long long)node * 64])[jq] = o;
            }
        }
        __syncthreads();
    }
}

// ---------------------------------------------------------------------------
// K4: per-edge (h[row]-h[col])^2, scatter-sum at row + fused out-degree.
// ---------------------------------------------------------------------------
__global__ void k_edge(const void* __restrict__ ei) {
    long long gtid = (long long)blockIdx.x * blockDim.x + threadIdx.x;
    long long e = gtid >> 4;
    int l = (int)(gtid & 15);
    if (e >= N_EDGES) return;
    int is64 = g_idx64;
    int r, c;
    load_edge(ei, e, is64, r, c);
    const float4* h4 = reinterpret_cast<const float4*>(g_h);
    float4 u = h4[(long long)r * 16 + l];
    float4 v = h4[(long long)c * 16 + l];
    float dx = u.x - v.x, dy = u.y - v.y, dz = u.z - v.z, dw = u.w - v.w;
    red_add_v4(&g_gg[(long long)r * 64 + l * 4],
               dx * dx, dy * dy, dz * dz, dw * dw);
    if (l == 0) atomicAdd(&g_outdeg[r], 1.f);
}

// ---------------------------------------------------------------------------
__global__ void k_final(float* __restrict__ out) {
    int i = blockIdx.x * blockDim.x + threadIdx.x;
    int stride = gridDim.x * blockDim.x;
    for (int idx = i; idx < N_NODES * D; idx += stride) {
        int node = idx >> 6;
        float m = g_gg[idx] / fmaxf(g_outdeg[node], 1.f);
        out[idx] = tanhf(m);
    }
}

// ---------------------------------------------------------------------------
extern "C" void kernel_launch(void* const* d_in, const int* in_sizes, int n_in,
                              void* d_out, int out_size) {
    const float* X  = (const float*)d_in[0];
    const void*  ei = d_in[1];
    const float* Wl = (const float*)d_in[2];
    const float* Wr = (const float*)d_in[3];
    const float* b  = (const float*)d_in[4];
    float* out = (float*)d_out;

    const int KH_SMEM = 24576 * sizeof(float);   // 96 KB
    static int attr_done = 0;
    if (!attr_done) {
        cudaFuncSetAttribute(k_h, cudaFuncAttributeMaxDynamicSharedMemorySize,
                             KH_SMEM);
        attr_done = 1;
    }

    k_zero<<<2048, 256>>>((const long long*)ei);
    {
        long long total = (long long)N_EDGES * 16;
        int blocks = (int)((total + 255) / 256);
        k_scatter<<<blocks, 256>>>((const float4*)X, ei);
    }
    k_h<<<782, 256, KH_SMEM>>>(X, Wl, Wr, b);
    {
        long long total = (long long)N_EDGES * 16;
        int blocks = (int)((total + 255) / 256);
        k_edge<<<blocks, 256>>>(ei);
    }
    k_final<<<2048, 256>>>(out);
}

// round 9
// speedup vs baseline: 1.4005x; 1.4005x over previous
#include <cuda_runtime.h>

#define N_NODES 100000
#define D       64
#define N_EDGES 1250000
#define NBLK    98            // ceil(N_NODES / 1024) scan blocks per array

// ---- scratch (allocation-free rule: __device__ globals) ----
__device__ __align__(16) float g_agg[N_NODES * D];   // mean of X[src] at dst
__device__ __align__(16) float g_h[N_NODES * D];     // relu(agg@Wl + b + X@Wr)
__device__ int g_incnt[N_NODES];
__device__ int g_outcnt[N_NODES];
__device__ int g_inptr[N_NODES + 1];
__device__ int g_outptr[N_NODES + 1];
__device__ int g_incur[N_NODES];
__device__ int g_outcur[N_NODES];
__device__ int g_adj_in[N_EDGES];     // src per dst-sorted edge
__device__ int g_adj_out[N_EDGES];    // dst per src-sorted edge
__device__ int g_bsum[2 * NBLK];
__device__ int g_idx64;

// Edge accessor robust to int32-vs-int64 edge_index.
__device__ __forceinline__ void load_edge(const void* __restrict__ ei,
                                          int e, int is64, int& r, int& c) {
    if (is64) {
        const long long* p = (const long long*)ei;
        r = (int)p[e];
        c = (int)p[N_EDGES + e];
    } else {
        const int* p = (const int*)ei;
        r = p[e];
        c = p[N_EDGES + e];
    }
}

// ---------------------------------------------------------------------------
// K1: zero histograms + dtype detect. Runs every replay.
// ---------------------------------------------------------------------------
__global__ void k_init(const long long* __restrict__ ei64) {
    int i = blockIdx.x * blockDim.x + threadIdx.x;
    if (i == 0) {
        int ok = 1;
        for (int k = 0; k < 32; k++) {
            long long v = ei64[k];
            if (v < 0 || v >= N_NODES) { ok = 0; break; }
        }
        g_idx64 = ok;
    }
    if (i < N_NODES) { g_incnt[i] = 0; g_outcnt[i] = 0; }
}

// ---------------------------------------------------------------------------
// K2: degree histograms.
// ---------------------------------------------------------------------------
__global__ void k_hist(const void* __restrict__ ei) {
    int e = blockIdx.x * blockDim.x + threadIdx.x;
    if (e >= N_EDGES) return;
    int is64 = g_idx64;
    int r, c;
    load_edge(ei, e, is64, r, c);
    atomicAdd(&g_outcnt[r], 1);
    atomicAdd(&g_incnt[c], 1);
}

// ---------------------------------------------------------------------------
// K3a: per-block exclusive scan (1024 elems/block). blocks [0,98): incnt,
//      blocks [98,196): outcnt.
// ---------------------------------------------------------------------------
__global__ __launch_bounds__(1024) void k_scan1() {
    __shared__ int ss[1024];
    int arr = blockIdx.x < NBLK ? 0 : 1;
    int blk = arr == 0 ? blockIdx.x : blockIdx.x - NBLK;
    int idx = blk * 1024 + threadIdx.x;
    const int* cnt = arr == 0 ? g_incnt : g_outcnt;
    int* ptr = arr == 0 ? g_inptr : g_outptr;
    int val = (idx < N_NODES) ? cnt[idx] : 0;
    ss[threadIdx.x] = val;
    __syncthreads();
#pragma unroll
    for (int off = 1; off < 1024; off <<= 1) {
        int t = (threadIdx.x >= off) ? ss[threadIdx.x - off] : 0;
        __syncthreads();
        ss[threadIdx.x] += t;
        __syncthreads();
    }
    if (idx < N_NODES) ptr[idx] = ss[threadIdx.x] - val;   // exclusive
    if (threadIdx.x == 1023) g_bsum[blockIdx.x] = ss[1023];
}

// K3b: scan the 2x98 block sums (serial in smem, 2 threads).
__global__ void k_scan2() {
    __shared__ int sb[2 * NBLK];
    int t = threadIdx.x;
    if (t < 2 * NBLK) sb[t] = g_bsum[t];
    __syncthreads();
    if (t == 0) {
        int run = 0;
        for (int i = 0; i < NBLK; i++) { int v = sb[i]; sb[i] = run; run += v; }
    } else if (t == 1) {
        int run = 0;
        for (int i = NBLK; i < 2 * NBLK; i++) { int v = sb[i]; sb[i] = run; run += v; }
    }
    __syncthreads();
    if (t < 2 * NBLK) g_bsum[t] = sb[t];
}

// K3c: add block offsets; init cursors; set sentinels.
__global__ __launch_bounds__(1024) void k_scan3() {
    int arr = blockIdx.x < NBLK ? 0 : 1;
    int blk = arr == 0 ? blockIdx.x : blockIdx.x - NBLK;
    int idx = blk * 1024 + threadIdx.x;
    int off = g_bsum[blockIdx.x];
    if (idx < N_NODES) {
        if (arr == 0) { int v = g_inptr[idx] + off;  g_inptr[idx] = v;  g_incur[idx] = v; }
        else          { int v = g_outptr[idx] + off; g_outptr[idx] = v; g_outcur[idx] = v; }
    }
    if (blockIdx.x == 0 && threadIdx.x == 0) {
        g_inptr[N_NODES] = N_EDGES;
        g_outptr[N_NODES] = N_EDGES;
    }
}

// ---------------------------------------------------------------------------
// K4: permute edges into both adjacency arrays.
// ---------------------------------------------------------------------------
__global__ void k_permute(const void* __restrict__ ei) {
    int e = blockIdx.x * blockDim.x + threadIdx.x;
    if (e >= N_EDGES) return;
    int is64 = g_idx64;
    int r, c;
    load_edge(ei, e, is64, r, c);
    int p0 = atomicAdd(&g_incur[c], 1);
    g_adj_in[p0] = r;
    int p1 = atomicAdd(&g_outcur[r], 1);
    g_adj_out[p1] = c;
}

// ---------------------------------------------------------------------------
// K5: agg[v] = mean over in-neighbors of X[src]. Warp per node, lane = float2.
// ---------------------------------------------------------------------------
__global__ __launch_bounds__(256) void k_agg(const float2* __restrict__ X2) {
    int warp = (blockIdx.x * blockDim.x + threadIdx.x) >> 5;
    int lane = threadIdx.x & 31;
    if (warp >= N_NODES) return;
    int s = g_inptr[warp];
    int e = g_inptr[warp + 1];
    float2 acc = make_float2(0.f, 0.f);
    int j = s;
    for (; j + 1 < e; j += 2) {
        int c0 = g_adj_in[j];
        int c1 = g_adj_in[j + 1];
        float2 v0 = __ldg(&X2[(long long)c0 * 32 + lane]);
        float2 v1 = __ldg(&X2[(long long)c1 * 32 + lane]);
        acc.x += v0.x + v1.x;
        acc.y += v0.y + v1.y;
    }
    if (j < e) {
        int c0 = g_adj_in[j];
        float2 v0 = __ldg(&X2[(long long)c0 * 32 + lane]);
        acc.x += v0.x; acc.y += v0.y;
    }
    float inv = 1.f / (float)max(e - s, 1);
    float2 o = make_float2(acc.x * inv, acc.y * inv);
    reinterpret_cast<float2*>(g_agg)[(long long)warp * 32 + lane] = o;
}

// ---------------------------------------------------------------------------
// K6: h = relu( agg @ Wl + b + X @ Wr ). (R7-proven config: 64-node tile,
// thread = 4 nodes x 4 outputs, 64 KB dynamic smem, grid 444.)
// ---------------------------------------------------------------------------
__global__ __launch_bounds__(256) void k_h(const float* __restrict__ X,
                                           const float* __restrict__ Wl,
                                           const float* __restrict__ Wr,
                                           const float* __restrict__ b) {
    extern __shared__ float s[];
    float* sWl = s;
    float* sWr = s + 4096;
    float* saT = s + 8192;
    float* sxT = s + 12288;

    int t = threadIdx.x;
    for (int i = t; i < 4096; i += 256) { sWl[i] = Wl[i]; sWr[i] = Wr[i]; }

    const int jq = t & 15;
    const int ng = t >> 4;
    const float4 bias = reinterpret_cast<const float4*>(b)[jq];
    __syncthreads();

    const float4* A4 = reinterpret_cast<const float4*>(g_agg);
    const float4* X4 = reinterpret_cast<const float4*>(X);

    for (int base = blockIdx.x * 64; base < N_NODES; base += gridDim.x * 64) {
#pragma unroll
        for (int p = 0; p < 4; p++) {
            int fi = t + p * 256;
            int node = fi & 63;
            int kq = fi >> 6;
            int gnode = base + node;
            float4 va, vx;
            if (gnode < N_NODES) {
                va = A4[(long long)gnode * 16 + kq];
                vx = X4[(long long)gnode * 16 + kq];
            } else {
                va = make_float4(0.f, 0.f, 0.f, 0.f);
                vx = va;
            }
            int kb = kq * 4;
            saT[(kb + 0) * 64 + node] = va.x;
            saT[(kb + 1) * 64 + node] = va.y;
            saT[(kb + 2) * 64 + node] = va.z;
            saT[(kb + 3) * 64 + node] = va.w;
            sxT[(kb + 0) * 64 + node] = vx.x;
            sxT[(kb + 1) * 64 + node] = vx.y;
            sxT[(kb + 2) * 64 + node] = vx.z;
            sxT[(kb + 3) * 64 + node] = vx.w;
        }
        __syncthreads();

        float acc[4][4];
#pragma unroll
        for (int i = 0; i < 4; i++) {
            acc[i][0] = bias.x; acc[i][1] = bias.y;
            acc[i][2] = bias.z; acc[i][3] = bias.w;
        }
#pragma unroll 8
        for (int k = 0; k < 64; k++) {
            float4 a4 = *reinterpret_cast<float4*>(&saT[k * 64 + ng * 4]);
            float4 x4 = *reinterpret_cast<float4*>(&sxT[k * 64 + ng * 4]);
            float4 wl = *reinterpret_cast<float4*>(&sWl[k * 64 + jq * 4]);
            float4 wr = *reinterpret_cast<float4*>(&sWr[k * 64 + jq * 4]);
            float av[4] = {a4.x, a4.y, a4.z, a4.w};
            float xv[4] = {x4.x, x4.y, x4.z, x4.w};
            float wlv[4] = {wl.x, wl.y, wl.z, wl.w};
            float wrv[4] = {wr.x, wr.y, wr.z, wr.w};
#pragma unroll
            for (int i = 0; i < 4; i++)
#pragma unroll
                for (int j = 0; j < 4; j++)
                    acc[i][j] += av[i] * wlv[j] + xv[i] * wrv[j];
        }

#pragma unroll
        for (int i = 0; i < 4; i++) {
            int node = base + ng * 4 + i;
            if (node < N_NODES) {
                float4 o;
                o.x = fmaxf(acc[i][0], 0.f);
                o.y = fmaxf(acc[i][1], 0.f);
                o.z = fmaxf(acc[i][2], 0.f);
                o.w = fmaxf(acc[i][3], 0.f);
                reinterpret_cast<float4*>(&g_h[(long long)node * 64])[jq] = o;
            }
        }
        __syncthreads();
    }
}

// ---------------------------------------------------------------------------
// K7: out[r] = tanh( mean over out-neighbors of (h[r]-h[c])^2 ).
//     Warp per node; h[r] held in registers; writes final output directly.
// ---------------------------------------------------------------------------
__global__ __launch_bounds__(256) void k_edge_csr(float2* __restrict__ out) {
    int warp = (blockIdx.x * blockDim.x + threadIdx.x) >> 5;
    int lane = threadIdx.x & 31;
    if (warp >= N_NODES) return;
    const float2* h2 = reinterpret_cast<const float2*>(g_h);
    float2 hr = h2[(long long)warp * 32 + lane];
    int s = g_outptr[warp];
    int e = g_outptr[warp + 1];
    float2 acc = make_float2(0.f, 0.f);
    int j = s;
    for (; j + 1 < e; j += 2) {
        int c0 = g_adj_out[j];
        int c1 = g_adj_out[j + 1];
        float2 v0 = __ldg(&h2[(long long)c0 * 32 + lane]);
        float2 v1 = __ldg(&h2[(long long)c1 * 32 + lane]);
        float d0x = hr.x - v0.x, d0y = hr.y - v0.y;
        float d1x = hr.x - v1.x, d1y = hr.y - v1.y;
        acc.x += d0x * d0x + d1x * d1x;
        acc.y += d0y * d0y + d1y * d1y;
    }
    if (j < e) {
        int c0 = g_adj_out[j];
        float2 v0 = __ldg(&h2[(long long)c0 * 32 + lane]);
        float dx = hr.x - v0.x, dy = hr.y - v0.y;
        acc.x += dx * dx;
        acc.y += dy * dy;
    }
    float inv = 1.f / (float)max(e - s, 1);
    float2 o = make_float2(tanhf(acc.x * inv), tanhf(acc.y * inv));
    out[(long long)warp * 32 + lane] = o;
}

// ---------------------------------------------------------------------------
extern "C" void kernel_launch(void* const* d_in, const int* in_sizes, int n_in,
                              void* d_out, int out_size) {
    const float* X  = (const float*)d_in[0];
    const void*  ei = d_in[1];
    const float* Wl = (const float*)d_in[2];
    const float* Wr = (const float*)d_in[3];
    const float* b  = (const float*)d_in[4];
    float* out = (float*)d_out;

    const int KH_SMEM = 16384 * sizeof(float);   // 64 KB
    static int attr_done = 0;
    if (!attr_done) {
        cudaFuncSetAttribute(k_h, cudaFuncAttributeMaxDynamicSharedMemorySize,
                             KH_SMEM);
        attr_done = 1;
    }

    k_init<<<(N_NODES + 1023) / 1024, 1024>>>((const long long*)ei);
    k_hist<<<(N_EDGES + 511) / 512, 512>>>(ei);
    k_scan1<<<2 * NBLK, 1024>>>();
    k_scan2<<<1, 256>>>();
    k_scan3<<<2 * NBLK, 1024>>>();
    k_permute<<<(N_EDGES + 511) / 512, 512>>>(ei);
    k_agg<<<(N_NODES * 32 + 255) / 256, 256>>>((const float2*)X);
    k_h<<<444, 256, KH_SMEM>>>(X, Wl, Wr, b);
    k_edge_csr<<<(N_NODES * 32 + 255) / 256, 256>>>((float2*)out);
}